// round 1
// baseline (speedup 1.0000x reference)
#include <cuda_runtime.h>
#include <math.h>

// Per-point precomputed data: 9 floats
// [0]=nb  (-b)        b = T10^2 + T11^2      (x^2 coeff)
// [1]=nc  (-c)        c = 2(T00*T10+T01*T11) (xy coeff)
// [2]=nE  (-E)        E = -(2 b lx + c ly)   (x coeff)
// [3]=na  (-a)        a = T00^2 + T01^2      (y^2 coeff)
// [4]=nD  (-D)        D = -(2 a ly + c lx)   (y coeff)
// [5]=F1  (1-F)       F = a ly^2 + b lx^2 + c lx ly
// [6..8] = color*alpha (r,g,b)
#define MAXP 4096
__device__ float g_pdata[MAXP * 9];

__global__ void prep_kernel(const float* __restrict__ loc,
                            const float* __restrict__ moff,
                            const float* __restrict__ msfo,
                            const float* __restrict__ colors,
                            const float* __restrict__ alphas,
                            int P)
{
    int p = blockIdx.x * blockDim.x + threadIdx.x;
    if (p >= P) return;

    float scale = 0.5f * sqrtf((float)P) * expf(msfo[p]);
    float T00 = moff[p * 4 + 0] + scale;
    float T01 = moff[p * 4 + 1];
    float T10 = moff[p * 4 + 2];
    float T11 = moff[p * 4 + 3] + scale;

    float a = T00 * T00 + T01 * T01;
    float b = T10 * T10 + T11 * T11;
    float c = 2.0f * (T00 * T10 + T01 * T11);

    float ly = loc[p * 2 + 0];
    float lx = loc[p * 2 + 1];

    float D = -(2.0f * a * ly + c * lx);
    float E = -(2.0f * b * lx + c * ly);
    float F = a * ly * ly + b * lx * lx + c * lx * ly;

    float al = alphas[p];

    float* q = g_pdata + p * 9;
    q[0] = -b;
    q[1] = -c;
    q[2] = -E;
    q[3] = -a;
    q[4] = -D;
    q[5] = 1.0f - F;
    q[6] = colors[p * 3 + 0] * al;
    q[7] = colors[p * 3 + 1] * al;
    q[8] = colors[p * 3 + 2] * al;
}

#define PXT 4          // pixels per thread (strided by blockDim)
#define TPB 128        // threads per block; one block == one canvas row

__global__ __launch_bounds__(TPB)
void render_kernel(float* __restrict__ out, int H, int W, int P, float ratio)
{
    extern __shared__ float s[];   // 9 * P floats

    // Stage the point table into shared memory
    const int nf = 9 * P;
    for (int i = threadIdx.x; i < nf; i += TPB) s[i] = g_pdata[i];
    __syncthreads();

    const int row = blockIdx.x;
    const float y = -1.0f + (float)row * (2.0f / (float)(H - 1));

    float x[PXT];
#pragma unroll
    for (int k = 0; k < PXT; k++) {
        int xi = threadIdx.x + k * TPB;
        x[k] = -ratio + (float)xi * (2.0f * ratio / (float)(W - 1));
    }

    float ar[PXT], ag[PXT], ab[PXT];
#pragma unroll
    for (int k = 0; k < PXT; k++) { ar[k] = 0.0f; ag[k] = 0.0f; ab[k] = 0.0f; }

#pragma unroll 4
    for (int p = 0; p < P; p++) {
        const float* q = s + p * 9;
        float nb = q[0], nc = q[1], nE = q[2];
        float na = q[3], nD = q[4], F1 = q[5];
        float wr = q[6], wg = q[7], wb = q[8];

        // per-(point,row) terms, amortized over PXT pixels
        float ng = fmaf(y, nc, nE);
        float h1 = fmaf(y, fmaf(y, na, nD), F1);

#pragma unroll
        for (int k = 0; k < PXT; k++) {
            // m = relu(1 - d) = max(h1 + ng*x + nb*x^2, 0)
            float w = fmaf(x[k], fmaf(x[k], nb, ng), h1);
            float m = fmaxf(w, 0.0f);
            ar[k] = fmaf(m, wr, ar[k]);
            ag[k] = fmaf(m, wg, ag[k]);
            ab[k] = fmaf(m, wb, ab[k]);
        }
    }

    // sigmoid(4*canvas) epilogue + store
#pragma unroll
    for (int k = 0; k < PXT; k++) {
        int xi = threadIdx.x + k * TPB;
        if (xi < W) {
            float r = 1.0f / (1.0f + __expf(-4.0f * ar[k]));
            float g = 1.0f / (1.0f + __expf(-4.0f * ag[k]));
            float b = 1.0f / (1.0f + __expf(-4.0f * ab[k]));
            int base = (row * W + xi) * 3;
            out[base + 0] = r;
            out[base + 1] = g;
            out[base + 2] = b;
        }
    }
}

extern "C" void kernel_launch(void* const* d_in, const int* in_sizes, int n_in,
                              void* d_out, int out_size)
{
    // Inputs (metadata order):
    // 0: canvas_height (int scalar, device)   1: canvas_width (int scalar, device)
    // 2: locations (1,1,P,2) f32              3: matrix_offsets (P,2,2) f32
    // 4: matrix_scale_factor_offsets (P,1,1)  5: colors (1,1,P,3) f32
    // 6: alphas (1,1,P,1) f32
    const float* loc    = (const float*)d_in[2];
    const float* moff   = (const float*)d_in[3];
    const float* msfo   = (const float*)d_in[4];
    const float* colors = (const float*)d_in[5];
    const float* alphas = (const float*)d_in[6];
    float* out = (float*)d_out;

    int P = in_sizes[2] / 2;             // locations has P*2 elements
    int HW = out_size / 3;               // output is H*W*3
    int H = (int)(sqrt((double)HW) + 0.5);
    int W = HW / H;
    float ratio = (float)W / (float)H;

    prep_kernel<<<(P + 127) / 128, 128>>>(loc, moff, msfo, colors, alphas, P);

    size_t smem = (size_t)(9 * P) * sizeof(float);
    render_kernel<<<H, TPB, smem>>>(out, H, W, P, ratio);
}